// round 1
// baseline (speedup 1.0000x reference)
#include <cuda_runtime.h>

#define NPART  524288
#define NMODE  8
#define NPSI   512
#define A0STR  520            // padded stride for transposed alpha0 table in smem
#define THREADS 256

__global__ __launch_bounds__(THREADS)
void eik_main(const float* __restrict__ tsc,
              const float* __restrict__ r,
              const float* __restrict__ varphi,
              const float* __restrict__ z,
              const float* __restrict__ psi,
              const float* __restrict__ gh_re,
              const float* __restrict__ gh_im,
              const float* __restrict__ a0_tab,     // [NPSI][NMODE]
              const float* __restrict__ iota_tab,   // [NPSI]
              const float* __restrict__ psi0,
              const float* __restrict__ psi_scale,
              const float* __restrict__ alpha_scale,
              const float* __restrict__ omega,
              const int*   __restrict__ nmode,
              float2* __restrict__ out)
{
    __shared__ float sh_a0[NMODE * A0STR];  // transposed: [mode][psi]
    __shared__ float sh_iota[NPSI];
    __shared__ float sh_par[NMODE][32];     // derived per-mode constants

    const int tid = threadIdx.x;

    // Stage tables into shared memory (transpose alpha0 on the fly).
    for (int idx = tid; idx < NPSI * NMODE; idx += THREADS) {
        int ii = idx >> 3;          // psi row
        int mm = idx & 7;           // mode
        sh_a0[mm * A0STR + ii] = a0_tab[idx];
    }
    for (int idx = tid; idx < NPSI; idx += THREADS)
        sh_iota[idx] = iota_tab[idx];

    // Threads 0..7 compute derived per-mode constants.
    if (tid < NMODE) {
        const int m = tid;
        const float t   = tsc[0];
        const float pss = psi_scale[m];
        const float ass = alpha_scale[m];
        const float ips = 1.0f / pss;
        const float ias = 1.0f / ass;
        const float nf  = (float)nmode[m];
        sh_par[m][0] = ips;
        sh_par[m][1] = -psi0[m] * ips;   // x = fma(psi, ips, mps0)
        sh_par[m][2] = ias;
        sh_par[m][3] = nf * ass;         // nas: phase = ph0 + nas*y
        sh_par[m][4] = nf;
        sh_par[m][5] = omega[m] * t;
        #pragma unroll
        for (int s = 0; s < 4; s++) {
            // s: 0 -> (re,f0), 1 -> (re,f1), 2 -> (im,f0), 3 -> (im,f1)
            const float* gh = (s < 2) ? gh_re : gh_im;
            const int f = s & 1;
            const float c0 = gh[m*12 + 0*2 + f];
            const float c1 = gh[m*12 + 1*2 + f];
            const float c2 = gh[m*12 + 2*2 + f];
            const float c3 = gh[m*12 + 3*2 + f];
            const float c4 = gh[m*12 + 4*2 + f];
            const float c5 = gh[m*12 + 5*2 + f];
            // p = c0 + c1 x + c2 y + c3(4x^2-2) + c4 x y + c5(4y^2-2)
            //   = [d0 + c1 x + q x^2] + y [b0 + c4 x] + C y^2
            sh_par[m][6 + s*6 + 0] = c0 - 2.0f*c3 - 2.0f*c5;  // d0
            sh_par[m][6 + s*6 + 1] = c1;
            sh_par[m][6 + s*6 + 2] = 4.0f*c3;                  // q
            sh_par[m][6 + s*6 + 3] = c2;                       // b0
            sh_par[m][6 + s*6 + 4] = c4;
            sh_par[m][6 + s*6 + 5] = 4.0f*c5;                  // C
        }
    }
    __syncthreads();

    const int gid = blockIdx.x * THREADS + tid;
    const float rr = r[gid];
    const float zz = z[gid];
    const float ps = psi[gid];
    const float vp = varphi[gid];

    const float TWO_PI_F = 6.28318530717958647692f;  // rounds to float(2*pi)
    const float theta = atan2f(zz, rr - 1.7f);

    // Catmull-Rom setup (match reference: s = psi / float32(DX))
    const float DXf = (float)(1.0 / 511.0);
    const float s  = ps / DXf;
    int i = (int)floorf(s);
    i = (i < 1) ? 1 : ((i > NPSI - 3) ? (NPSI - 3) : i);
    const float ttv = s - (float)i;
    const float t2 = ttv * ttv;
    const float t3 = t2 * ttv;
    const float wm1 = 0.5f * (-t3 + 2.0f * t2 - ttv);
    const float w0  = 0.5f * (3.0f * t3 - 5.0f * t2 + 2.0f);
    const float w1  = 0.5f * (-3.0f * t3 + 4.0f * t2 + ttv);
    const float w2  = 0.5f * (t3 - t2);

    const float io = wm1 * sh_iota[i-1] + w0 * sh_iota[i]
                   + w1  * sh_iota[i+1] + w2 * sh_iota[i+2];

    const float al0 = io * (theta - TWO_PI_F);
    const float al1 = io * theta;
    const float al2 = io * (theta + TWO_PI_F);

    // Sin/cos range reduction constants (2-step Cody-Waite around 2*pi)
    const float INV2PI  = 0.15915494309189535f;
    const float MAGIC   = 12582912.0f;            // 1.5 * 2^23
    const float PI2_HI  = 6.28318548202514648f;   // float(2*pi)
    const float PI2_LO  = -1.7484555e-07f;        // 2*pi - PI2_HI

    float acc0 = 0.0f, acc1 = 0.0f;

    #pragma unroll
    for (int m = 0; m < NMODE; m++) {
        const float* P = sh_par[m];
        const float ips  = P[0];
        const float mps0 = P[1];
        const float ias  = P[2];
        const float nas  = P[3];
        const float nf   = P[4];
        const float wt   = P[5];

        // alpha0 interpolation for this mode (smem gather, random i per lane)
        const float* A = &sh_a0[m * A0STR];
        const float a0m = wm1 * A[i-1] + w0 * A[i] + w1 * A[i+1] + w2 * A[i+2];

        const float x  = fmaf(ps, ips, mps0);
        const float x2 = x * x;
        const float ph0 = fmaf(-nf, vp, wt);     // omega*t - n*varphi

        float Aa[4], Bb[4], Cc[4];
        #pragma unroll
        for (int s2 = 0; s2 < 4; s2++) {
            const float d0 = P[6 + s2*6 + 0];
            const float c1 = P[6 + s2*6 + 1];
            const float q  = P[6 + s2*6 + 2];
            const float b0 = P[6 + s2*6 + 3];
            const float c4 = P[6 + s2*6 + 4];
            Cc[s2] = P[6 + s2*6 + 5];
            Aa[s2] = fmaf(q, x2, fmaf(c1, x, d0));
            Bb[s2] = fmaf(c4, x, b0);
        }

        #pragma unroll
        for (int k = 0; k < 3; k++) {
            const float alk = (k == 0) ? al0 : ((k == 1) ? al1 : al2);
            const float y = (alk - a0m) * ias;

            const float g = __expf(-0.5f * fmaf(y, y, x2));

            float phase = fmaf(nas, y, ph0);
            // reduce phase into [-pi, pi]
            const float kq = fmaf(phase, INV2PI, MAGIC) - MAGIC;
            float ph = fmaf(kq, -PI2_HI, phase);
            ph = fmaf(kq, -PI2_LO, ph);
            float sn, cs;
            __sincosf(ph, &sn, &cs);

            const float gc = g * cs;
            const float gs = g * sn;

            float p[4];
            #pragma unroll
            for (int s2 = 0; s2 < 4; s2++)
                p[s2] = fmaf(y, fmaf(Cc[s2], y, Bb[s2]), Aa[s2]);

            acc0 = fmaf(gc, p[0], acc0);
            acc1 = fmaf(gc, p[1], acc1);
            acc0 = fmaf(-gs, p[2], acc0);
            acc1 = fmaf(-gs, p[3], acc1);
        }
    }

    out[gid] = make_float2(acc0, acc1);
}

extern "C" void kernel_launch(void* const* d_in, const int* in_sizes, int n_in,
                              void* d_out, int out_size)
{
    (void)in_sizes; (void)n_in; (void)out_size;
    eik_main<<<NPART / THREADS, THREADS>>>(
        (const float*)d_in[0],   // t
        (const float*)d_in[1],   // r
        (const float*)d_in[2],   // varphi
        (const float*)d_in[3],   // z
        (const float*)d_in[4],   // psi
        (const float*)d_in[5],   // gh_re
        (const float*)d_in[6],   // gh_im
        (const float*)d_in[7],   // alpha0_table
        (const float*)d_in[8],   // iota_table
        (const float*)d_in[9],   // psi0
        (const float*)d_in[10],  // psi_scale
        (const float*)d_in[11],  // alpha_scale
        (const float*)d_in[12],  // omega
        (const int*)  d_in[13],  // n
        (float2*)d_out);
}

// round 2
// speedup vs baseline: 1.2188x; 1.2188x over previous
#include <cuda_runtime.h>

#define NPART  524288
#define NMODE  8
#define NPSI   512
#define THREADS 256

typedef unsigned long long u64;

__device__ __forceinline__ u64 pk(float lo, float hi) {
    u64 r; asm("mov.b64 %0, {%1, %2};" : "=l"(r) : "f"(lo), "f"(hi)); return r;
}
__device__ __forceinline__ u64 pk2(float v) { return pk(v, v); }
__device__ __forceinline__ void upk(u64 v, float& lo, float& hi) {
    asm("mov.b64 {%0, %1}, %2;" : "=f"(lo), "=f"(hi) : "l"(v));
}
__device__ __forceinline__ u64 fma2(u64 a, u64 b, u64 c) {
    u64 d; asm("fma.rn.f32x2 %0, %1, %2, %3;" : "=l"(d) : "l"(a), "l"(b), "l"(c)); return d;
}
__device__ __forceinline__ float ex2f(float a) {
    float r; asm("ex2.approx.ftz.f32 %0, %1;" : "=f"(r) : "f"(a)); return r;
}

__global__ __launch_bounds__(THREADS)
void eik_main(const float* __restrict__ tsc,
              const float* __restrict__ r,
              const float* __restrict__ varphi,
              const float* __restrict__ z,
              const float* __restrict__ psi,
              const float* __restrict__ gh_re,
              const float* __restrict__ gh_im,
              const float* __restrict__ a0_tab,     // [NPSI][NMODE]
              const float* __restrict__ iota_tab,   // [NPSI]
              const float* __restrict__ psi0,
              const float* __restrict__ psi_scale,
              const float* __restrict__ alpha_scale,
              const float* __restrict__ omega,
              const int*   __restrict__ nmode,
              float2* __restrict__ out)
{
    // a0 table: [psi][0]=modes0-3, [psi][1]=modes4-7, [psi][2]=pad (48B row stride)
    __shared__ float4 sh_a0v[NPSI][3];
    __shared__ float  sh_iota[NPSI];
    // per-mode params, 8 float4 each:
    // [0]={ips,mps0,ias,nas} [1]={nf,wt,0,0}
    // [2]=d0[s0..s3] [3]=c1[...] [4]=q [5]=b0 [6]=c4 [7]=C
    // series order: s0=(re,f0) s1=(re,f1) s2=(im,f0) s3=(im,f1)
    __shared__ float4 sh_par4[NMODE][8];

    const int tid = threadIdx.x;

    // Stage alpha0 table (vectorized rows)
    const float4* a0v = (const float4*)a0_tab;
    for (int idx = tid; idx < NPSI * 2; idx += THREADS)
        sh_a0v[idx >> 1][idx & 1] = a0v[idx];
    for (int idx = tid; idx < NPSI; idx += THREADS)
        sh_iota[idx] = iota_tab[idx];

    if (tid < NMODE) {
        const int m = tid;
        const float t   = tsc[0];
        const float ips = 1.0f / psi_scale[m];
        const float ass = alpha_scale[m];
        const float ias = 1.0f / ass;
        const float nf  = (float)nmode[m];
        float* P = (float*)&sh_par4[m][0];
        P[0] = ips;
        P[1] = -psi0[m] * ips;
        P[2] = ias;
        P[3] = nf * ass;          // nas
        P[4] = nf;
        P[5] = omega[m] * t;
        P[6] = 0.0f; P[7] = 0.0f;
        #pragma unroll
        for (int s = 0; s < 4; s++) {
            const float* gh = (s < 2) ? gh_re : gh_im;
            const int f = s & 1;
            const float c0 = gh[m*12 + 0*2 + f];
            const float c1 = gh[m*12 + 1*2 + f];
            const float c2 = gh[m*12 + 2*2 + f];
            const float c3 = gh[m*12 + 3*2 + f];
            const float c4 = gh[m*12 + 4*2 + f];
            const float c5 = gh[m*12 + 5*2 + f];
            P[8  + s] = c0 - 2.0f*c3 - 2.0f*c5;  // d0
            P[12 + s] = c1;
            P[16 + s] = 4.0f*c3;                 // q
            P[20 + s] = c2;                      // b0
            P[24 + s] = c4;
            P[28 + s] = 4.0f*c5;                 // C
        }
    }
    __syncthreads();

    const int gid = blockIdx.x * THREADS + tid;
    const float rr = r[gid];
    const float zz = z[gid];
    const float ps = psi[gid];
    const float vp = varphi[gid];

    const float TWO_PI_F = 6.28318530717958647692f;
    const float theta = atan2f(zz, rr - 1.7f);

    // Catmull-Rom setup
    const float DXf = (float)(1.0 / 511.0);
    const float s  = ps / DXf;
    int i = (int)floorf(s);
    i = (i < 1) ? 1 : ((i > NPSI - 3) ? (NPSI - 3) : i);
    const float ttv = s - (float)i;
    const float t2 = ttv * ttv;
    const float t3 = t2 * ttv;
    const float wm1 = 0.5f * (-t3 + 2.0f * t2 - ttv);
    const float w0  = 0.5f * (3.0f * t3 - 5.0f * t2 + 2.0f);
    const float w1  = 0.5f * (-3.0f * t3 + 4.0f * t2 + ttv);
    const float w2  = 0.5f * (t3 - t2);

    const float io = wm1 * sh_iota[i-1] + w0 * sh_iota[i]
                   + w1  * sh_iota[i+1] + w2 * sh_iota[i+2];

    // alpha0 interpolation for ALL 8 modes (vectorized gather, hoisted)
    float a0m[NMODE];
    {
        float4 A0 = sh_a0v[i-1][0], B0 = sh_a0v[i-1][1];
        float4 A1 = sh_a0v[i  ][0], B1 = sh_a0v[i  ][1];
        float4 A2 = sh_a0v[i+1][0], B2 = sh_a0v[i+1][1];
        float4 A3 = sh_a0v[i+2][0], B3 = sh_a0v[i+2][1];
        a0m[0] = wm1*A0.x + w0*A1.x + w1*A2.x + w2*A3.x;
        a0m[1] = wm1*A0.y + w0*A1.y + w1*A2.y + w2*A3.y;
        a0m[2] = wm1*A0.z + w0*A1.z + w1*A2.z + w2*A3.z;
        a0m[3] = wm1*A0.w + w0*A1.w + w1*A2.w + w2*A3.w;
        a0m[4] = wm1*B0.x + w0*B1.x + w1*B2.x + w2*B3.x;
        a0m[5] = wm1*B0.y + w0*B1.y + w1*B2.y + w2*B3.y;
        a0m[6] = wm1*B0.z + w0*B1.z + w1*B2.z + w2*B3.z;
        a0m[7] = wm1*B0.w + w0*B1.w + w1*B2.w + w2*B3.w;
    }

    const float al1 = io * theta;       // alpha at shift 0
    const float dal = io * TWO_PI_F;    // alpha spacing between branches

    const float INV2PI  = 0.15915494309189535f;
    const float MAGIC   = 12582912.0f;            // 1.5 * 2^23
    const float PI2_HI  = 6.28318548202514648f;
    const float PI2_LO  = -1.7484555e-07f;
    const float NHL2E   = -0.72134752044448170368f;  // -0.5*log2(e)

    u64 acc = pk(0.0f, 0.0f);  // (field0, field1)

    #pragma unroll
    for (int m = 0; m < NMODE; m++) {
        const float4 p0 = sh_par4[m][0];  // ips, mps0, ias, nas
        const float4 p1 = sh_par4[m][1];  // nf, wt
        const ulonglong2 d0p = *(const ulonglong2*)&sh_par4[m][2];
        const ulonglong2 c1p = *(const ulonglong2*)&sh_par4[m][3];
        const ulonglong2 qp  = *(const ulonglong2*)&sh_par4[m][4];
        const ulonglong2 b0p = *(const ulonglong2*)&sh_par4[m][5];
        const ulonglong2 c4p = *(const ulonglong2*)&sh_par4[m][6];
        const ulonglong2 Cp  = *(const ulonglong2*)&sh_par4[m][7];

        const float x  = fmaf(ps, p0.x, p0.y);
        const float x2 = x * x;
        const float ph0 = fmaf(-p1.x, vp, p1.y);
        const float x2h = x2 * NHL2E;       // -0.5*log2(e)*x^2

        const u64 xp  = pk2(x);
        const u64 x2p = pk2(x2);
        const u64 Aa_re = fma2(qp.x, x2p, fma2(c1p.x, xp, d0p.x));
        const u64 Aa_im = fma2(qp.y, x2p, fma2(c1p.y, xp, d0p.y));
        const u64 Bb_re = fma2(c4p.x, xp, b0p.x);
        const u64 Bb_im = fma2(c4p.y, xp, b0p.y);

        const float y1  = (al1 - a0m[m]) * p0.z;
        const float dlt = dal * p0.z;        // y spacing
        const float Dph = p0.w * dlt;        // phase spacing = n*iota*2pi
        const float ph1 = fmaf(p0.w, y1, ph0);

        // reduce ph1 into [-pi, pi]
        float k1 = fmaf(ph1, INV2PI, MAGIC) - MAGIC;
        float phr = fmaf(k1, -PI2_HI, ph1);
        phr = fmaf(k1, -PI2_LO, phr);
        float s1, c1; __sincosf(phr, &s1, &c1);

        // reduce Dph
        float kD = fmaf(Dph, INV2PI, MAGIC) - MAGIC;
        float Dr = fmaf(kD, -PI2_HI, Dph);
        Dr = fmaf(kD, -PI2_LO, Dr);
        float sD, cD; __sincosf(Dr, &sD, &cD);

        // branches 0,2 via angle addition
        const float pc  = c1 * cD;
        const float psn = s1 * cD;
        const float c0b = fmaf( s1, sD, pc);   // cos(ph1 - Dph)
        const float c2b = fmaf(-s1, sD, pc);   // cos(ph1 + Dph)
        const float s0b = fmaf(-c1, sD, psn);  // sin(ph1 - Dph)
        const float s2b = fmaf( c1, sD, psn);  // sin(ph1 + Dph)

        const float y0v = y1 - dlt;
        const float y2v = y1 + dlt;

        #pragma unroll
        for (int k = 0; k < 3; k++) {
            const float yk = (k == 0) ? y0v : ((k == 1) ? y1 : y2v);
            const float ck = (k == 0) ? c0b : ((k == 1) ? c1 : c2b);
            const float sk = (k == 0) ? s0b : ((k == 1) ? s1 : s2b);

            const float yh = yk * NHL2E;
            const float ek = ex2f(fmaf(yh, yk, x2h));  // exp(-0.5(x^2+y^2))

            const u64 yp = pk2(yk);
            const u64 pre = fma2(yp, fma2(Cp.x, yp, Bb_re), Aa_re);
            const u64 pim = fma2(yp, fma2(Cp.y, yp, Bb_im), Aa_im);

            const float gc = ek * ck;
            const float gs = -ek * sk;
            acc = fma2(pk2(gc), pre, acc);
            acc = fma2(pk2(gs), pim, acc);
        }
    }

    float o0, o1;
    upk(acc, o0, o1);
    out[gid] = make_float2(o0, o1);
}

extern "C" void kernel_launch(void* const* d_in, const int* in_sizes, int n_in,
                              void* d_out, int out_size)
{
    (void)in_sizes; (void)n_in; (void)out_size;
    eik_main<<<NPART / THREADS, THREADS>>>(
        (const float*)d_in[0],   // t
        (const float*)d_in[1],   // r
        (const float*)d_in[2],   // varphi
        (const float*)d_in[3],   // z
        (const float*)d_in[4],   // psi
        (const float*)d_in[5],   // gh_re
        (const float*)d_in[6],   // gh_im
        (const float*)d_in[7],   // alpha0_table
        (const float*)d_in[8],   // iota_table
        (const float*)d_in[9],   // psi0
        (const float*)d_in[10],  // psi_scale
        (const float*)d_in[11],  // alpha_scale
        (const float*)d_in[12],  // omega
        (const int*)  d_in[13],  // n
        (float2*)d_out);
}

// round 3
// speedup vs baseline: 1.2436x; 1.0204x over previous
#include <cuda_runtime.h>

#define NPART  524288
#define NMODE  8
#define NPSI   512
#define THREADS 128
#define PPT     2

typedef unsigned long long u64;

__device__ __forceinline__ u64 pk(float lo, float hi) {
    u64 r; asm("mov.b64 %0, {%1, %2};" : "=l"(r) : "f"(lo), "f"(hi)); return r;
}
__device__ __forceinline__ u64 pk2(float v) { return pk(v, v); }
__device__ __forceinline__ void upk(u64 v, float& lo, float& hi) {
    asm("mov.b64 {%0, %1}, %2;" : "=f"(lo), "=f"(hi) : "l"(v));
}
__device__ __forceinline__ u64 fma2(u64 a, u64 b, u64 c) {
    u64 d; asm("fma.rn.f32x2 %0, %1, %2, %3;" : "=l"(d) : "l"(a), "l"(b), "l"(c)); return d;
}
__device__ __forceinline__ float ex2f(float a) {
    float r; asm("ex2.approx.ftz.f32 %0, %1;" : "=f"(r) : "f"(a)); return r;
}
__device__ __forceinline__ float sinap(float a) {
    float r; asm("sin.approx.ftz.f32 %0, %1;" : "=f"(r) : "f"(a)); return r;
}
__device__ __forceinline__ float cosap(float a) {
    float r; asm("cos.approx.ftz.f32 %0, %1;" : "=f"(r) : "f"(a)); return r;
}

__global__ __launch_bounds__(THREADS)
void eik_main(const float* __restrict__ tsc,
              const float* __restrict__ r,
              const float* __restrict__ varphi,
              const float* __restrict__ z,
              const float* __restrict__ psi,
              const float* __restrict__ gh_re,
              const float* __restrict__ gh_im,
              const float* __restrict__ a0_tab,     // [NPSI][NMODE]
              const float* __restrict__ iota_tab,   // [NPSI]
              const float* __restrict__ psi0,
              const float* __restrict__ psi_scale,
              const float* __restrict__ alpha_scale,
              const float* __restrict__ omega,
              const int*   __restrict__ nmode,
              float2* __restrict__ out)
{
    // row: [0]=a0 modes0-3, [1]=a0 modes4-7, [2].x=iota (rest pad)
    __shared__ float4 sh_tab[NPSI][3];
    // per-mode params, 8 float4 each:
    // [0]={ips,mps0,ias,nas} [1]={negnf,wt,0,0}
    // [2]=d0[s0..s3] [3]=c1 [4]=q [5]=b0 [6]=c4 [7]=C
    // series order: s0=(re,f0) s1=(re,f1) s2=(im,f0) s3=(im,f1)
    __shared__ float4 sh_par4[NMODE][8];

    const int tid = threadIdx.x;

    const float4* a0v = (const float4*)a0_tab;
    for (int idx = tid; idx < NPSI * 2; idx += THREADS)
        sh_tab[idx >> 1][idx & 1] = a0v[idx];
    for (int idx = tid; idx < NPSI; idx += THREADS)
        sh_tab[idx][2].x = iota_tab[idx];

    if (tid < NMODE) {
        const int m = tid;
        const float t   = tsc[0];
        const float ips = 1.0f / psi_scale[m];
        const float ass = alpha_scale[m];
        const float nf  = (float)nmode[m];
        float* P = (float*)&sh_par4[m][0];
        P[0] = ips;
        P[1] = -psi0[m] * ips;
        P[2] = 1.0f / ass;
        P[3] = nf * ass;          // nas
        P[4] = -nf;
        P[5] = omega[m] * t;
        P[6] = 0.0f; P[7] = 0.0f;
        #pragma unroll
        for (int s = 0; s < 4; s++) {
            const float* gh = (s < 2) ? gh_re : gh_im;
            const int f = s & 1;
            const float c0 = gh[m*12 + 0*2 + f];
            const float c1 = gh[m*12 + 1*2 + f];
            const float c2 = gh[m*12 + 2*2 + f];
            const float c3 = gh[m*12 + 3*2 + f];
            const float c4 = gh[m*12 + 4*2 + f];
            const float c5 = gh[m*12 + 5*2 + f];
            P[8  + s] = c0 - 2.0f*c3 - 2.0f*c5;  // d0
            P[12 + s] = c1;
            P[16 + s] = 4.0f*c3;                 // q
            P[20 + s] = c2;                      // b0
            P[24 + s] = c4;
            P[28 + s] = 4.0f*c5;                 // C
        }
    }
    __syncthreads();

    const int base = blockIdx.x * (THREADS * PPT) + tid;

    const float TWO_PI_F = 6.28318530717958647692f;
    const float DXf = (float)(1.0 / 511.0);
    const float INV2PI  = 0.15915494309189535f;
    const float MAGIC   = 12582912.0f;            // 1.5 * 2^23
    const float PI2_HI  = 6.28318548202514648f;
    const float PI2_LO  = -1.7484555e-07f;
    const float NHL2E   = -0.72134752044448170368f;  // -0.5*log2(e)

    float ps[PPT], vp[PPT], al1[PPT], dal[PPT];
    u64 am01[PPT], am23[PPT], am45[PPT], am67[PPT];   // alpha0 interp, mode pairs

    #pragma unroll
    for (int p = 0; p < PPT; p++) {
        const int gid = base + p * THREADS;
        const float rr = r[gid];
        const float zz = z[gid];
        ps[p] = psi[gid];
        vp[p] = varphi[gid];

        const float theta = atan2f(zz, rr - 1.7f);

        const float s = ps[p] / DXf;
        int i = (int)floorf(s);
        i = (i < 1) ? 1 : ((i > NPSI - 3) ? (NPSI - 3) : i);
        const float ttv = s - (float)i;
        const float t2 = ttv * ttv;
        const float t3 = t2 * ttv;
        const float wm1 = 0.5f * (-t3 + 2.0f * t2 - ttv);
        const float w0  = 0.5f * (3.0f * t3 - 5.0f * t2 + 2.0f);
        const float w1  = 0.5f * (-3.0f * t3 + 4.0f * t2 + ttv);
        const float w2  = 0.5f * (t3 - t2);

        const float io = wm1 * sh_tab[i-1][2].x + w0 * sh_tab[i][2].x
                       + w1  * sh_tab[i+1][2].x + w2 * sh_tab[i+2][2].x;

        const ulonglong2 R0v = *(const ulonglong2*)&sh_tab[i-1][0];
        const ulonglong2 R0w = *(const ulonglong2*)&sh_tab[i-1][1];
        const ulonglong2 R1v = *(const ulonglong2*)&sh_tab[i  ][0];
        const ulonglong2 R1w = *(const ulonglong2*)&sh_tab[i  ][1];
        const ulonglong2 R2v = *(const ulonglong2*)&sh_tab[i+1][0];
        const ulonglong2 R2w = *(const ulonglong2*)&sh_tab[i+1][1];
        const ulonglong2 R3v = *(const ulonglong2*)&sh_tab[i+2][0];
        const ulonglong2 R3w = *(const ulonglong2*)&sh_tab[i+2][1];
        const u64 wm1p = pk2(wm1), w0p = pk2(w0), w1p = pk2(w1), w2p = pk2(w2);
        const u64 zz2 = pk(0.0f, 0.0f);
        am01[p] = fma2(w2p, R3v.x, fma2(w1p, R2v.x, fma2(w0p, R1v.x, fma2(wm1p, R0v.x, zz2))));
        am23[p] = fma2(w2p, R3v.y, fma2(w1p, R2v.y, fma2(w0p, R1v.y, fma2(wm1p, R0v.y, zz2))));
        am45[p] = fma2(w2p, R3w.x, fma2(w1p, R2w.x, fma2(w0p, R1w.x, fma2(wm1p, R0w.x, zz2))));
        am67[p] = fma2(w2p, R3w.y, fma2(w1p, R2w.y, fma2(w0p, R1w.y, fma2(wm1p, R0w.y, zz2))));

        al1[p] = io * theta;
        dal[p] = io * TWO_PI_F;
    }

    u64 acc[PPT];
    #pragma unroll
    for (int p = 0; p < PPT; p++) acc[p] = pk(0.0f, 0.0f);

    #pragma unroll
    for (int m = 0; m < NMODE; m++) {
        const float4 q0 = sh_par4[m][0];  // ips, mps0, ias, nas
        const float4 q1 = sh_par4[m][1];  // negnf, wt
        const ulonglong2 d0p = *(const ulonglong2*)&sh_par4[m][2];
        const ulonglong2 c1p = *(const ulonglong2*)&sh_par4[m][3];
        const ulonglong2 qp  = *(const ulonglong2*)&sh_par4[m][4];
        const ulonglong2 b0p = *(const ulonglong2*)&sh_par4[m][5];
        const ulonglong2 c4p = *(const ulonglong2*)&sh_par4[m][6];
        const ulonglong2 Cp  = *(const ulonglong2*)&sh_par4[m][7];

        #pragma unroll
        for (int p = 0; p < PPT; p++) {
            // extract a0m for this (particle, mode)
            float a0lo, a0hi, a0m;
            if (m < 2)      upk(am01[p], a0lo, a0hi);
            else if (m < 4) upk(am23[p], a0lo, a0hi);
            else if (m < 6) upk(am45[p], a0lo, a0hi);
            else            upk(am67[p], a0lo, a0hi);
            a0m = (m & 1) ? a0hi : a0lo;

            const float x  = fmaf(ps[p], q0.x, q0.y);
            const float x2 = x * x;
            const float ph0 = fmaf(q1.x, vp[p], q1.y);  // wt - n*vp
            const float x2h = x2 * NHL2E;

            const u64 xp  = pk2(x);
            const u64 x2p = pk2(x2);
            const u64 Aa_re = fma2(qp.x, x2p, fma2(c1p.x, xp, d0p.x));
            const u64 Aa_im = fma2(qp.y, x2p, fma2(c1p.y, xp, d0p.y));
            const u64 Bb_re = fma2(c4p.x, xp, b0p.x);
            const u64 Bb_im = fma2(c4p.y, xp, b0p.y);

            const float y1  = (al1[p] - a0m) * q0.z;
            const float dlt = dal[p] * q0.z;
            const float Dph = q0.w * dlt;
            const float ph1 = fmaf(q0.w, y1, ph0);

            float k1 = fmaf(ph1, INV2PI, MAGIC) - MAGIC;
            float phr = fmaf(k1, -PI2_HI, ph1);
            phr = fmaf(k1, -PI2_LO, phr);
            const float s1 = sinap(phr);
            const float c1 = cosap(phr);

            float kD = fmaf(Dph, INV2PI, MAGIC) - MAGIC;
            float Dr = fmaf(kD, -PI2_HI, Dph);
            Dr = fmaf(kD, -PI2_LO, Dr);
            const float sD = sinap(Dr);
            const float cD = cosap(Dr);

            const float pc  = c1 * cD;
            const float psn = s1 * cD;
            const float c0b = fmaf( s1, sD, pc);
            const float c2b = fmaf(-s1, sD, pc);
            const float s0b = fmaf(-c1, sD, psn);
            const float s2b = fmaf( c1, sD, psn);

            const float y0v = y1 - dlt;
            const float y2v = y1 + dlt;

            #pragma unroll
            for (int k = 0; k < 3; k++) {
                const float yk = (k == 0) ? y0v : ((k == 1) ? y1 : y2v);
                const float ck = (k == 0) ? c0b : ((k == 1) ? c1 : c2b);
                const float sk = (k == 0) ? s0b : ((k == 1) ? s1 : s2b);

                const float yh = yk * NHL2E;
                const float ek = ex2f(fmaf(yh, yk, x2h));

                const u64 yp = pk2(yk);
                const u64 pre = fma2(yp, fma2(Cp.x, yp, Bb_re), Aa_re);
                const u64 pim = fma2(yp, fma2(Cp.y, yp, Bb_im), Aa_im);

                const float gc = ek * ck;
                const float gs = -ek * sk;
                acc[p] = fma2(pk2(gc), pre, acc[p]);
                acc[p] = fma2(pk2(gs), pim, acc[p]);
            }
        }
    }

    #pragma unroll
    for (int p = 0; p < PPT; p++) {
        float o0, o1;
        upk(acc[p], o0, o1);
        out[base + p * THREADS] = make_float2(o0, o1);
    }
}

extern "C" void kernel_launch(void* const* d_in, const int* in_sizes, int n_in,
                              void* d_out, int out_size)
{
    (void)in_sizes; (void)n_in; (void)out_size;
    eik_main<<<NPART / (THREADS * PPT), THREADS>>>(
        (const float*)d_in[0],   // t
        (const float*)d_in[1],   // r
        (const float*)d_in[2],   // varphi
        (const float*)d_in[3],   // z
        (const float*)d_in[4],   // psi
        (const float*)d_in[5],   // gh_re
        (const float*)d_in[6],   // gh_im
        (const float*)d_in[7],   // alpha0_table
        (const float*)d_in[8],   // iota_table
        (const float*)d_in[9],   // psi0
        (const float*)d_in[10],  // psi_scale
        (const float*)d_in[11],  // alpha_scale
        (const float*)d_in[12],  // omega
        (const int*)  d_in[13],  // n
        (float2*)d_out);
}

// round 4
// speedup vs baseline: 1.2452x; 1.0013x over previous
#include <cuda_runtime.h>

#define NPART  524288
#define NMODE  8
#define NPSI   512
#define THREADS 256
#define PPT     2

typedef unsigned long long u64;

// Derived per-mode parameters: 32 floats per mode.
// [0]=ips [1]=mps0 [2]=ias [3]=nas [4]=negnf [5]=wt [6..7]=pad
// [8..11]=d0[s0..s3] [12..15]=c1 [16..19]=q [20..23]=b0 [24..27]=c4 [28..31]=C
// series order: s0=(re,f0) s1=(re,f1) s2=(im,f0) s3=(im,f1)
__device__   float g_par[NMODE * 32];
__constant__ float c_par[NMODE * 32];

__device__ __forceinline__ u64 pk(float lo, float hi) {
    u64 r; asm("mov.b64 %0, {%1, %2};" : "=l"(r) : "f"(lo), "f"(hi)); return r;
}
__device__ __forceinline__ u64 pk2(float v) { return pk(v, v); }
__device__ __forceinline__ void upk(u64 v, float& lo, float& hi) {
    asm("mov.b64 {%0, %1}, %2;" : "=f"(lo), "=f"(hi) : "l"(v));
}
__device__ __forceinline__ u64 fma2(u64 a, u64 b, u64 c) {
    u64 d; asm("fma.rn.f32x2 %0, %1, %2, %3;" : "=l"(d) : "l"(a), "l"(b), "l"(c)); return d;
}
__device__ __forceinline__ float ex2f(float a) {
    float r; asm("ex2.approx.ftz.f32 %0, %1;" : "=f"(r) : "f"(a)); return r;
}
__device__ __forceinline__ float sinap(float a) {
    float r; asm("sin.approx.ftz.f32 %0, %1;" : "=f"(r) : "f"(a)); return r;
}
__device__ __forceinline__ float cosap(float a) {
    float r; asm("cos.approx.ftz.f32 %0, %1;" : "=f"(r) : "f"(a)); return r;
}

__global__ void eik_prep(const float* __restrict__ tsc,
                         const float* __restrict__ gh_re,
                         const float* __restrict__ gh_im,
                         const float* __restrict__ psi0,
                         const float* __restrict__ psi_scale,
                         const float* __restrict__ alpha_scale,
                         const float* __restrict__ omega,
                         const int*   __restrict__ nmode)
{
    const int m = threadIdx.x;
    if (m >= NMODE) return;
    const float t   = tsc[0];
    const float ips = 1.0f / psi_scale[m];
    const float ass = alpha_scale[m];
    const float nf  = (float)nmode[m];
    float* P = &g_par[m * 32];
    P[0] = ips;
    P[1] = -psi0[m] * ips;
    P[2] = 1.0f / ass;
    P[3] = nf * ass;          // nas
    P[4] = -nf;
    P[5] = omega[m] * t;
    P[6] = 0.0f; P[7] = 0.0f;
    #pragma unroll
    for (int s = 0; s < 4; s++) {
        const float* gh = (s < 2) ? gh_re : gh_im;
        const int f = s & 1;
        const float c0 = gh[m*12 + 0*2 + f];
        const float c1 = gh[m*12 + 1*2 + f];
        const float c2 = gh[m*12 + 2*2 + f];
        const float c3 = gh[m*12 + 3*2 + f];
        const float c4 = gh[m*12 + 4*2 + f];
        const float c5 = gh[m*12 + 5*2 + f];
        P[8  + s] = c0 - 2.0f*c3 - 2.0f*c5;  // d0
        P[12 + s] = c1;
        P[16 + s] = 4.0f*c3;                 // q
        P[20 + s] = c2;                      // b0
        P[24 + s] = c4;
        P[28 + s] = 4.0f*c5;                 // C
    }
}

__global__ __launch_bounds__(THREADS)
void eik_main(const float* __restrict__ r,
              const float* __restrict__ varphi,
              const float* __restrict__ z,
              const float* __restrict__ psi,
              const float* __restrict__ a0_tab,     // [NPSI][NMODE]
              const float* __restrict__ iota_tab,   // [NPSI]
              float2* __restrict__ out)
{
    // row: [0]=a0 modes0-3, [1]=a0 modes4-7, [2].x=iota (rest pad)
    __shared__ float4 sh_tab[NPSI][3];

    const int tid = threadIdx.x;

    const float4* a0v = (const float4*)a0_tab;
    for (int idx = tid; idx < NPSI * 2; idx += THREADS)
        sh_tab[idx >> 1][idx & 1] = a0v[idx];
    for (int idx = tid; idx < NPSI; idx += THREADS)
        sh_tab[idx][2].x = iota_tab[idx];
    __syncthreads();

    const int base = blockIdx.x * (THREADS * PPT) + tid;

    const float TWO_PI_F = 6.28318530717958647692f;
    const float DXf = (float)(1.0 / 511.0);
    const float INV2PI  = 0.15915494309189535f;
    const float MAGIC   = 12582912.0f;            // 1.5 * 2^23
    const float PI2_HI  = 6.28318548202514648f;
    const float PI2_LO  = -1.7484555e-07f;
    const float NHL2E   = -0.72134752044448170368f;  // -0.5*log2(e)

    float ps[PPT], vp[PPT], al1[PPT], dal[PPT];
    u64 am01[PPT], am23[PPT], am45[PPT], am67[PPT];

    #pragma unroll
    for (int p = 0; p < PPT; p++) {
        const int gid = base + p * THREADS;
        const float rr = r[gid];
        const float zz = z[gid];
        ps[p] = psi[gid];
        vp[p] = varphi[gid];

        const float theta = atan2f(zz, rr - 1.7f);

        const float s = ps[p] / DXf;
        int i = (int)floorf(s);
        i = (i < 1) ? 1 : ((i > NPSI - 3) ? (NPSI - 3) : i);
        const float ttv = s - (float)i;
        const float t2 = ttv * ttv;
        const float t3 = t2 * ttv;
        const float wm1 = 0.5f * (-t3 + 2.0f * t2 - ttv);
        const float w0  = 0.5f * (3.0f * t3 - 5.0f * t2 + 2.0f);
        const float w1  = 0.5f * (-3.0f * t3 + 4.0f * t2 + ttv);
        const float w2  = 0.5f * (t3 - t2);

        const float io = wm1 * sh_tab[i-1][2].x + w0 * sh_tab[i][2].x
                       + w1  * sh_tab[i+1][2].x + w2 * sh_tab[i+2][2].x;

        const ulonglong2 R0v = *(const ulonglong2*)&sh_tab[i-1][0];
        const ulonglong2 R0w = *(const ulonglong2*)&sh_tab[i-1][1];
        const ulonglong2 R1v = *(const ulonglong2*)&sh_tab[i  ][0];
        const ulonglong2 R1w = *(const ulonglong2*)&sh_tab[i  ][1];
        const ulonglong2 R2v = *(const ulonglong2*)&sh_tab[i+1][0];
        const ulonglong2 R2w = *(const ulonglong2*)&sh_tab[i+1][1];
        const ulonglong2 R3v = *(const ulonglong2*)&sh_tab[i+2][0];
        const ulonglong2 R3w = *(const ulonglong2*)&sh_tab[i+2][1];
        const u64 wm1p = pk2(wm1), w0p = pk2(w0), w1p = pk2(w1), w2p = pk2(w2);
        const u64 zz2 = pk(0.0f, 0.0f);
        am01[p] = fma2(w2p, R3v.x, fma2(w1p, R2v.x, fma2(w0p, R1v.x, fma2(wm1p, R0v.x, zz2))));
        am23[p] = fma2(w2p, R3v.y, fma2(w1p, R2v.y, fma2(w0p, R1v.y, fma2(wm1p, R0v.y, zz2))));
        am45[p] = fma2(w2p, R3w.x, fma2(w1p, R2w.x, fma2(w0p, R1w.x, fma2(wm1p, R0w.x, zz2))));
        am67[p] = fma2(w2p, R3w.y, fma2(w1p, R2w.y, fma2(w0p, R1w.y, fma2(wm1p, R0w.y, zz2))));

        al1[p] = io * theta;
        dal[p] = io * TWO_PI_F;
    }

    u64 acc[PPT];
    #pragma unroll
    for (int p = 0; p < PPT; p++) acc[p] = pk(0.0f, 0.0f);

    #pragma unroll
    for (int m = 0; m < NMODE; m++) {
        const float* P = &c_par[m * 32];
        const float ips  = P[0];
        const float mps0 = P[1];
        const float ias  = P[2];
        const float nas  = P[3];
        const float ngnf = P[4];
        const float wt   = P[5];
        const u64 d0_re = *(const u64*)&P[8];
        const u64 d0_im = *(const u64*)&P[10];
        const u64 c1_re = *(const u64*)&P[12];
        const u64 c1_im = *(const u64*)&P[14];
        const u64 q_re  = *(const u64*)&P[16];
        const u64 q_im  = *(const u64*)&P[18];
        const u64 b0_re = *(const u64*)&P[20];
        const u64 b0_im = *(const u64*)&P[22];
        const u64 c4_re = *(const u64*)&P[24];
        const u64 c4_im = *(const u64*)&P[26];
        const u64 C_re  = *(const u64*)&P[28];
        const u64 C_im  = *(const u64*)&P[30];

        #pragma unroll
        for (int p = 0; p < PPT; p++) {
            float a0lo, a0hi, a0m;
            if (m < 2)      upk(am01[p], a0lo, a0hi);
            else if (m < 4) upk(am23[p], a0lo, a0hi);
            else if (m < 6) upk(am45[p], a0lo, a0hi);
            else            upk(am67[p], a0lo, a0hi);
            a0m = (m & 1) ? a0hi : a0lo;

            const float x  = fmaf(ps[p], ips, mps0);
            const float x2 = x * x;
            const float ph0 = fmaf(ngnf, vp[p], wt);  // wt - n*vp
            const float x2h = x2 * NHL2E;

            const u64 xp  = pk2(x);
            const u64 x2p = pk2(x2);
            const u64 Aa_re = fma2(q_re, x2p, fma2(c1_re, xp, d0_re));
            const u64 Aa_im = fma2(q_im, x2p, fma2(c1_im, xp, d0_im));
            const u64 Bb_re = fma2(c4_re, xp, b0_re);
            const u64 Bb_im = fma2(c4_im, xp, b0_im);

            const float y1  = (al1[p] - a0m) * ias;
            const float dlt = dal[p] * ias;
            const float Dph = nas * dlt;
            const float ph1 = fmaf(nas, y1, ph0);

            float k1 = fmaf(ph1, INV2PI, MAGIC) - MAGIC;
            float phr = fmaf(k1, -PI2_HI, ph1);
            phr = fmaf(k1, -PI2_LO, phr);
            const float s1 = sinap(phr);
            const float c1 = cosap(phr);

            float kD = fmaf(Dph, INV2PI, MAGIC) - MAGIC;
            float Dr = fmaf(kD, -PI2_HI, Dph);
            Dr = fmaf(kD, -PI2_LO, Dr);
            const float sD = sinap(Dr);
            const float cD = cosap(Dr);

            const float pc  = c1 * cD;
            const float psn = s1 * cD;
            const float c0b = fmaf( s1, sD, pc);
            const float c2b = fmaf(-s1, sD, pc);
            const float s0b = fmaf(-c1, sD, psn);
            const float s2b = fmaf( c1, sD, psn);

            const float y0v = y1 - dlt;
            const float y2v = y1 + dlt;

            #pragma unroll
            for (int k = 0; k < 3; k++) {
                const float yk = (k == 0) ? y0v : ((k == 1) ? y1 : y2v);
                const float ck = (k == 0) ? c0b : ((k == 1) ? c1 : c2b);
                const float sk = (k == 0) ? s0b : ((k == 1) ? s1 : s2b);

                const float yh = yk * NHL2E;
                const float ek = ex2f(fmaf(yh, yk, x2h));

                const u64 yp = pk2(yk);
                const u64 pre = fma2(yp, fma2(C_re, yp, Bb_re), Aa_re);
                const u64 pim = fma2(yp, fma2(C_im, yp, Bb_im), Aa_im);

                const float gc = ek * ck;
                const float gs = -ek * sk;
                acc[p] = fma2(pk2(gc), pre, acc[p]);
                acc[p] = fma2(pk2(gs), pim, acc[p]);
            }
        }
    }

    #pragma unroll
    for (int p = 0; p < PPT; p++) {
        float o0, o1;
        upk(acc[p], o0, o1);
        out[base + p * THREADS] = make_float2(o0, o1);
    }
}

extern "C" void kernel_launch(void* const* d_in, const int* in_sizes, int n_in,
                              void* d_out, int out_size)
{
    (void)in_sizes; (void)n_in; (void)out_size;

    eik_prep<<<1, NMODE>>>(
        (const float*)d_in[0],   // t
        (const float*)d_in[5],   // gh_re
        (const float*)d_in[6],   // gh_im
        (const float*)d_in[9],   // psi0
        (const float*)d_in[10],  // psi_scale
        (const float*)d_in[11],  // alpha_scale
        (const float*)d_in[12],  // omega
        (const int*)  d_in[13]); // n

    void* c_addr = nullptr;
    void* g_addr = nullptr;
    cudaGetSymbolAddress(&c_addr, c_par);
    cudaGetSymbolAddress(&g_addr, g_par);
    cudaMemcpyAsync(c_addr, g_addr, NMODE * 32 * sizeof(float),
                    cudaMemcpyDeviceToDevice, 0);

    eik_main<<<NPART / (THREADS * PPT), THREADS>>>(
        (const float*)d_in[1],   // r
        (const float*)d_in[2],   // varphi
        (const float*)d_in[3],   // z
        (const float*)d_in[4],   // psi
        (const float*)d_in[7],   // alpha0_table
        (const float*)d_in[8],   // iota_table
        (float2*)d_out);
}